// round 10
// baseline (speedup 1.0000x reference)
#include <cuda_runtime.h>
#include <float.h>
#include <math.h>

#define BATCH 2
#define NPTS 8192
#define KNN 16
#define THREADS 128
#define NQ_TOTAL (2 * BATCH * NPTS)       // 32768 query slots
#define QPT 4                             // queries per thread in the scan
#define QBLK (THREADS * QPT)              // 512 queries per scan block
#define QBLOCKS (NQ_TOTAL / QBLK)         // 64
#define SPLITS 4
#define SPLIT_PTS (NPTS / SPLITS)         // 2048 ref points per scan block
#define NSCAN (SPLITS * QBLOCKS)          // 256 scan blocks
#define SELBLOCKS (NQ_TOTAL / THREADS)    // 256 (tau / select)
#define CAP 192                           // cand capacity / query / split (E~64)
#define SUB 512                           // threshold-pass subset size

__device__ float g_partials[SELBLOCKS];
__device__ float g_tau[NQ_TOTAL];
__device__ int   g_cnt[SPLITS * NQ_TOTAL];
__device__ float g_scratch[(size_t)SPLITS * CAP * NQ_TOTAL];   // ~100 MB static

// branch-free candidate emit; carried chain is selp(4)+add(4) only.
__device__ __forceinline__ float* cond_store(float* wp, float sc, float tau) {
    asm volatile(
        "{\n\t"
        ".reg .pred p;\n\t"
        ".reg .u64 inc;\n\t"
        "setp.le.f32 p, %1, %2;\n\t"
        "selp.u64 inc, %3, 0, p;\n\t"
        "@p st.global.f32 [%0], %1;\n\t"
        "add.u64 %0, %0, inc;\n\t"
        "}"
        : "+l"(wp)
        : "f"(sc), "f"(tau), "n"((unsigned long long)(NQ_TOTAL * sizeof(float)))
        : "memory");
    return wp;
}

// unconditional sorted-descending top-K insert (pure FMNMX, straight-line)
__device__ __forceinline__ void bubble_insert(float* best, float sc) {
    best[0] = fminf(best[0], sc);
#pragma unroll
    for (int i = 0; i < KNN - 1; i++) {
        const float a = best[i], c = best[i + 1];
        best[i]     = fmaxf(a, c);
        best[i + 1] = fminf(a, c);
    }
}

__device__ __forceinline__ void load_query(const float* __restrict__ src,
                                           const float* __restrict__ tgt,
                                           const float* __restrict__ flow,
                                           int gq, float& qx, float& qy, float& qz) {
    const int set = gq / NPTS;
    const int b   = set >> 1;
    const int dir = set & 1;
    const int qi  = gq - set * NPTS;
    const float* sb = src  + (size_t)b * NPTS * 3;
    const float* tb = tgt  + (size_t)b * NPTS * 3;
    const float* fb = flow + (size_t)b * NPTS * 3;
    if (dir == 0) {
        qx = sb[qi * 3 + 0] + fb[qi * 3 + 0];
        qy = sb[qi * 3 + 1] + fb[qi * 3 + 1];
        qz = sb[qi * 3 + 2] + fb[qi * 3 + 2];
    } else {
        qx = tb[qi * 3 + 0];
        qy = tb[qi * 3 + 1];
        qz = tb[qi * 3 + 2];
    }
}

// compute ref point g for query-set `set`: (x, y, z, w=|r|^2/2)
__device__ __forceinline__ float4 make_ref(const float* __restrict__ src,
                                           const float* __restrict__ tgt,
                                           const float* __restrict__ flow,
                                           int set, int g) {
    const int b   = set >> 1;
    const int dir = set & 1;
    const float* sb = src  + (size_t)b * NPTS * 3;
    const float* tb = tgt  + (size_t)b * NPTS * 3;
    const float* fb = flow + (size_t)b * NPTS * 3;
    float x, y, z;
    if (dir == 0) {             // query = pred, ref = target
        x = tb[g * 3 + 0]; y = tb[g * 3 + 1]; z = tb[g * 3 + 2];
    } else {                    // query = target, ref = pred = src + flow
        x = sb[g * 3 + 0] + fb[g * 3 + 0];
        y = sb[g * 3 + 1] + fb[g * 3 + 1];
        z = sb[g * 3 + 2] + fb[g * 3 + 2];
    }
    return make_float4(x, y, z, 0.5f * (x * x + (y * y + z * z)));
}

// exact 16th-smallest score over a 512-point subset -> g_tau
__global__ void __launch_bounds__(THREADS)
tau_kernel(const float* __restrict__ src,
           const float* __restrict__ tgt,
           const float* __restrict__ flow) {
    __shared__ float4 sub[SUB];
    const int tid = threadIdx.x;
    const int gq  = blockIdx.x * THREADS + tid;
    const int set = gq / NPTS;

    for (int p = tid; p < SUB; p += THREADS)
        sub[p] = make_ref(src, tgt, flow, set, p);

    float qx, qy, qz;
    load_query(src, tgt, flow, gq, qx, qy, qz);
    __syncthreads();

    float best[KNN];
#pragma unroll
    for (int i = 0; i < KNN; i++) best[i] = FLT_MAX;

    for (int j0 = 0; j0 < SUB; j0 += 8) {
        float sc[8];
#pragma unroll
        for (int jj = 0; jj < 8; jj++) {
            const float4 r = sub[j0 + jj];
            float t = fmaf(-qx, r.x, r.w);
            t = fmaf(-qy, r.y, t);
            sc[jj] = fmaf(-qz, r.z, t);
        }
#pragma unroll
        for (int jj = 0; jj < 8; jj++) bubble_insert(best, sc[jj]);
    }
    g_tau[gq] = best[0];
}

// stateless filter, 4 queries per thread: one broadcast load feeds 4 queries
__global__ void __launch_bounds__(THREADS)
scan_kernel(const float* __restrict__ src,
            const float* __restrict__ tgt,
            const float* __restrict__ flow) {
    __shared__ float sx[SPLIT_PTS], sy[SPLIT_PTS], sz[SPLIT_PTS], sw[SPLIT_PTS]; // 32 KB

    const int tid   = threadIdx.x;
    const int split = blockIdx.x >> 6;            // 0..3
    const int qblk  = blockIdx.x & 63;            // 0..63
    const int set   = (qblk * QBLK) / NPTS;       // all QPT queries share a set

    // stage this split's ref points (SoA)
    for (int p = tid; p < SPLIT_PTS; p += THREADS) {
        const float4 r = make_ref(src, tgt, flow, set, split * SPLIT_PTS + p);
        sx[p] = r.x; sy[p] = r.y; sz[p] = r.z; sw[p] = r.w;
    }

    float qx[QPT], qy[QPT], qz[QPT], tau[QPT];
    float* wp[QPT];
    float* wguard[QPT];
#pragma unroll
    for (int q = 0; q < QPT; q++) {
        const int gq = qblk * QBLK + q * THREADS + tid;
        load_query(src, tgt, flow, gq, qx[q], qy[q], qz[q]);
        tau[q]    = g_tau[gq];
        wp[q]     = g_scratch + (size_t)split * CAP * NQ_TOTAL + gq;
        wguard[q] = wp[q] + (size_t)(CAP - 16) * NQ_TOTAL;
    }
    __syncthreads();

    for (int j0 = 0; j0 < SPLIT_PTS; j0 += 16) {
        // overflow belts checked once per 16 points (never fire statistically)
#pragma unroll
        for (int q = 0; q < QPT; q++)
            tau[q] = (wp[q] >= wguard[q]) ? -FLT_MAX : tau[q];

#pragma unroll
        for (int g4 = 0; g4 < 16; g4 += 4) {
            // 4 vector loads serve 4 points x 4 queries
            const float4 X = *(const float4*)&sx[j0 + g4];
            const float4 Y = *(const float4*)&sy[j0 + g4];
            const float4 Z = *(const float4*)&sz[j0 + g4];
            const float4 W = *(const float4*)&sw[j0 + g4];
            const float xs[4] = {X.x, X.y, X.z, X.w};
            const float ys[4] = {Y.x, Y.y, Y.z, Y.w};
            const float zs[4] = {Z.x, Z.y, Z.z, Z.w};
            const float ws[4] = {W.x, W.y, W.z, W.w};

            float sc[QPT][4];
#pragma unroll
            for (int q = 0; q < QPT; q++) {
#pragma unroll
                for (int p = 0; p < 4; p++) {
                    float t = fmaf(-qx[q], xs[p], ws[p]);
                    t = fmaf(-qy[q], ys[p], t);
                    sc[q][p] = fmaf(-qz[q], zs[p], t);
                }
            }
#pragma unroll
            for (int q = 0; q < QPT; q++) {
#pragma unroll
                for (int p = 0; p < 4; p++)
                    wp[q] = cond_store(wp[q], sc[q][p], tau[q]);
            }
        }
    }

#pragma unroll
    for (int q = 0; q < QPT; q++) {
        const int gq = qblk * QBLK + q * THREADS + tid;
        float* base = g_scratch + (size_t)split * CAP * NQ_TOTAL + gq;
        g_cnt[split * NQ_TOTAL + gq] = (int)((wp[q] - base) / NQ_TOTAL);
    }
}

__global__ void __launch_bounds__(THREADS)
select_kernel(const float* __restrict__ src,
              const float* __restrict__ tgt,
              const float* __restrict__ flow) {
    const int tid = threadIdx.x;
    const int gq  = blockIdx.x * THREADS + tid;

    float qx, qy, qz;
    load_query(src, tgt, flow, gq, qx, qy, qz);
    const float q2 = qx * qx + qy * qy + qz * qz;

    float best[KNN];
#pragma unroll
    for (int i = 0; i < KNN; i++) best[i] = FLT_MAX;

#pragma unroll
    for (int split = 0; split < SPLITS; split++) {
        const float* const rbase = g_scratch + (size_t)split * CAP * NQ_TOTAL + gq;
        const int cnt  = g_cnt[split * NQ_TOTAL + gq];
        const int mcnt = __reduce_max_sync(0xffffffffu, cnt);
        for (int i = 0; i < mcnt; i += 4) {
            float v[4];
#pragma unroll
            for (int u = 0; u < 4; u++) {
                const int idx = i + u;
                float t = (idx < mcnt) ? rbase[(size_t)idx * NQ_TOTAL] : FLT_MAX;
                v[u] = (idx < cnt) ? t : FLT_MAX;
            }
#pragma unroll
            for (int u = 0; u < 4; u++) bubble_insert(best, v[u]);
        }
    }

    // sum of the 16 euclidean distances: d = sqrt(2*score + |q|^2)
    float s = 0.f;
#pragma unroll
    for (int i = 0; i < KNN; i++) {
        const float d2 = fmaf(2.f, best[i], q2);
        s += sqrtf(fmaxf(d2, 0.f));
    }

    __shared__ float warpsum[THREADS / 32];
#pragma unroll
    for (int o = 16; o > 0; o >>= 1) s += __shfl_down_sync(0xffffffffu, s, o);
    if ((tid & 31) == 0) warpsum[tid >> 5] = s;
    __syncthreads();
    if (tid == 0) {
        float tot = 0.f;
#pragma unroll
        for (int w = 0; w < THREADS / 32; w++) tot += warpsum[w];
        g_partials[blockIdx.x] = tot;
    }
}

__global__ void __launch_bounds__(SELBLOCKS)
finalize_kernel(float* __restrict__ out) {
    __shared__ float sh[SELBLOCKS];
    const int tid = threadIdx.x;
    sh[tid] = g_partials[tid];
    __syncthreads();
#pragma unroll
    for (int s = SELBLOCKS / 2; s > 0; s >>= 1) {
        if (tid < s) sh[tid] += sh[tid + s];
        __syncthreads();
    }
    if (tid == 0) {
        out[0] = sh[0] * (1.0f / (float)(KNN * BATCH * NPTS));
    }
}

extern "C" void kernel_launch(void* const* d_in, const int* in_sizes, int n_in,
                              void* d_out, int out_size) {
    const float* src  = (const float*)d_in[0];   // pc_source [B, N, 3]
    const float* tgt  = (const float*)d_in[1];   // pc_target [B, M, 3]
    const float* flow = (const float*)d_in[2];   // pred_flow [B, N, 3]
    float* out = (float*)d_out;

    tau_kernel<<<SELBLOCKS, THREADS>>>(src, tgt, flow);
    scan_kernel<<<NSCAN, THREADS>>>(src, tgt, flow);
    select_kernel<<<SELBLOCKS, THREADS>>>(src, tgt, flow);
    finalize_kernel<<<1, SELBLOCKS>>>(out);
}

// round 11
// speedup vs baseline: 1.1848x; 1.1848x over previous
#include <cuda_runtime.h>
#include <float.h>
#include <math.h>

#define BATCH 2
#define NPTS 8192
#define KNN 16
#define TILE 2048                       // 2048 * 16B = 32 KB static smem
#define THREADS 128
#define NBLOCKS (2 * BATCH * NPTS / THREADS)   // 256
#define NQ_TOTAL (2 * BATCH * NPTS)            // 32768
#define CAP 1024                        // candidate capacity per query
#define SUB 512                         // threshold-pass subset size
#define UNR 8

__device__ float g_partials[NBLOCKS];
__device__ unsigned int g_done;                       // zero-init; self-resetting
__device__ float g_scratch[(size_t)CAP * NQ_TOTAL];   // 134 MB static scratch

// branch-free candidate emit; carried chain is selp(4)+add(4) only.
__device__ __forceinline__ float* cond_store(float* wp, float sc, float tau) {
    asm volatile(
        "{\n\t"
        ".reg .pred p;\n\t"
        ".reg .u64 inc;\n\t"
        "setp.le.f32 p, %1, %2;\n\t"
        "selp.u64 inc, %3, 0, p;\n\t"
        "@p st.global.f32 [%0], %1;\n\t"
        "add.u64 %0, %0, inc;\n\t"
        "}"
        : "+l"(wp)
        : "f"(sc), "f"(tau), "n"((unsigned long long)(NQ_TOTAL * sizeof(float)))
        : "memory");
    return wp;
}

// unconditional sorted-descending top-K insert (pure FMNMX, straight-line)
__device__ __forceinline__ void bubble_insert(float* best, float sc) {
    best[0] = fminf(best[0], sc);
#pragma unroll
    for (int i = 0; i < KNN - 1; i++) {
        const float a = best[i], c = best[i + 1];
        best[i]     = fmaxf(a, c);
        best[i + 1] = fminf(a, c);
    }
}

__global__ void __launch_bounds__(THREADS)
chamfer_knn_kernel(const float* __restrict__ src,
                   const float* __restrict__ tgt,
                   const float* __restrict__ flow,
                   float* __restrict__ out) {
    __shared__ float4 spts[TILE];

    const int tid = threadIdx.x;
    const int gq  = blockIdx.x * THREADS + tid;       // global query slot
    const int blocks_per_set = NPTS / THREADS;        // 64
    const int set = blockIdx.x / blocks_per_set;      // (batch, direction)
    const int b   = set >> 1;
    const int dir = set & 1;                          // 0: pred->target, 1: target->pred
    const int qi  = (blockIdx.x % blocks_per_set) * THREADS + tid;

    const float* __restrict__ srcb = src  + (size_t)b * NPTS * 3;
    const float* __restrict__ tgtb = tgt  + (size_t)b * NPTS * 3;
    const float* __restrict__ flob = flow + (size_t)b * NPTS * 3;

    float qx, qy, qz;
    if (dir == 0) {
        qx = srcb[qi * 3 + 0] + flob[qi * 3 + 0];
        qy = srcb[qi * 3 + 1] + flob[qi * 3 + 1];
        qz = srcb[qi * 3 + 2] + flob[qi * 3 + 2];
    } else {
        qx = tgtb[qi * 3 + 0];
        qy = tgtb[qi * 3 + 1];
        qz = tgtb[qi * 3 + 2];
    }
    const float q2 = qx * qx + qy * qy + qz * qz;

    float best[KNN];
#pragma unroll
    for (int i = 0; i < KNN; i++) best[i] = FLT_MAX;

    float tau = FLT_MAX;
    float* const wbase  = g_scratch + gq;
    float*       wp     = wbase;
    float* const wguard = wbase + (size_t)(CAP - UNR) * NQ_TOTAL;

    for (int t0 = 0; t0 < NPTS; t0 += TILE) {
        // stage ref tile as (x, y, z, |r|^2/2)
        for (int p = tid; p < TILE; p += THREADS) {
            const int g = t0 + p;
            float x, y, z;
            if (dir == 0) {
                x = tgtb[g * 3 + 0];
                y = tgtb[g * 3 + 1];
                z = tgtb[g * 3 + 2];
            } else {
                x = srcb[g * 3 + 0] + flob[g * 3 + 0];
                y = srcb[g * 3 + 1] + flob[g * 3 + 1];
                z = srcb[g * 3 + 2] + flob[g * 3 + 2];
            }
            const float w = 0.5f * (x * x + (y * y + z * z));
            spts[p] = make_float4(x, y, z, w);
        }
        __syncthreads();

        if (t0 == 0) {
            // threshold pass: batch-load/score UNR points, then bubble them
            for (int j0 = 0; j0 < SUB; j0 += UNR) {
                float sc[UNR];
#pragma unroll
                for (int jj = 0; jj < UNR; jj++) {
                    const float4 r = spts[j0 + jj];
                    float t = fmaf(-qx, r.x, r.w);
                    t = fmaf(-qy, r.y, t);
                    sc[jj] = fmaf(-qz, r.z, t);
                }
#pragma unroll
                for (int jj = 0; jj < UNR; jj++) bubble_insert(best, sc[jj]);
            }
            tau = best[0];   // upper bound on true 16th-smallest score
        }

        // streaming collect: batched loads/scores, then branch-free stores
        for (int j0 = 0; j0 < TILE; j0 += UNR) {
            tau = (wp >= wguard) ? -FLT_MAX : tau;   // SEL, never fires statistically
            float sc[UNR];
#pragma unroll
            for (int jj = 0; jj < UNR; jj++) {
                const float4 r = spts[j0 + jj];
                float t = fmaf(-qx, r.x, r.w);
                t = fmaf(-qy, r.y, t);
                sc[jj] = fmaf(-qz, r.z, t);
            }
#pragma unroll
            for (int jj = 0; jj < UNR; jj++) wp = cond_store(wp, sc[jj], tau);
        }
        __syncthreads();
    }

    // final exact selection over collected candidates (superset of true top-16)
    const int cnt  = (int)((wp - wbase) / NQ_TOTAL);
    const int mcnt = __reduce_max_sync(0xffffffffu, cnt);
#pragma unroll
    for (int i = 0; i < KNN; i++) best[i] = FLT_MAX;   // reinit: avoid double count

    for (int i = 0; i < mcnt; i += 4) {
        float v[4];
#pragma unroll
        for (int u = 0; u < 4; u++) {
            const int idx = i + u;
            float t = (idx < mcnt) ? wbase[(size_t)idx * NQ_TOTAL] : FLT_MAX;
            v[u] = (idx < cnt) ? t : FLT_MAX;
        }
#pragma unroll
        for (int u = 0; u < 4; u++) bubble_insert(best, v[u]);
    }

    // sum of the 16 euclidean distances: d = sqrt(2*score + |q|^2)
    float s = 0.f;
#pragma unroll
    for (int i = 0; i < KNN; i++) {
        const float d2 = fmaf(2.f, best[i], q2);
        s += sqrtf(fmaxf(d2, 0.f));
    }

    // deterministic block reduction
    __shared__ float warpsum[THREADS / 32];
#pragma unroll
    for (int o = 16; o > 0; o >>= 1) s += __shfl_down_sync(0xffffffffu, s, o);
    if ((tid & 31) == 0) warpsum[tid >> 5] = s;
    __syncthreads();

    // last-block-done: single-kernel deterministic global reduction
    __shared__ unsigned int s_rank;
    if (tid == 0) {
        float tot = 0.f;
#pragma unroll
        for (int w = 0; w < THREADS / 32; w++) tot += warpsum[w];
        g_partials[blockIdx.x] = tot;
        __threadfence();
        s_rank = atomicAdd(&g_done, 1u);
    }
    __syncthreads();
    if (s_rank == NBLOCKS - 1) {
        // this block finished last: all partials are visible (fence + atomic order)
        float tot = 0.f;
        // fixed-order serial sum -> bitwise deterministic output
        if (tid == 0) {
            for (int i = 0; i < NBLOCKS; i++) tot += g_partials[i];
            out[0] = tot * (1.0f / (float)(KNN * BATCH * NPTS));
            g_done = 0;            // self-reset for next graph replay
        }
    }
}

extern "C" void kernel_launch(void* const* d_in, const int* in_sizes, int n_in,
                              void* d_out, int out_size) {
    const float* src  = (const float*)d_in[0];   // pc_source [B, N, 3]
    const float* tgt  = (const float*)d_in[1];   // pc_target [B, M, 3]
    const float* flow = (const float*)d_in[2];   // pred_flow [B, N, 3]
    float* out = (float*)d_out;

    chamfer_knn_kernel<<<NBLOCKS, THREADS>>>(src, tgt, flow, out);
}